// round 12
// baseline (speedup 1.0000x reference)
#include <cuda_runtime.h>
#include <cuda_bf16.h>
#include <math.h>
#include <stdint.h>

#define F_IN 512
#define HID  256
#define NCLS 40
#define MAXN 100000
#define MAXE 1600000

// ---- scratch ----
__device__ float g_h1  [(size_t)MAXN * HID];
__device__ float g_agg1[(size_t)MAXN * HID];
__device__ float g_h2  [(size_t)MAXN * NCLS];
__device__ float g_dinv[MAXN];
__device__ int   g_cnt [MAXN];
__device__ int   g_rowstart[MAXN + 1];
__device__ int   g_cursor[MAXN];
__device__ int   g_se[MAXE];
__device__ float g_ce[MAXE];
__device__ int   g_bsum[128];
__device__ __nv_bfloat16 g_w1hi[(size_t)HID * F_IN];   // [n][k] transposed
__device__ __nv_bfloat16 g_w1lo[(size_t)HID * F_IN];

#define MMA_BF16(c, a, b) \
    asm volatile("mma.sync.aligned.m16n8k16.row.col.f32.bf16.bf16.f32 " \
                 "{%0,%1,%2,%3}, {%4,%5,%6,%7}, {%8,%9}, {%0,%1,%2,%3};" \
                 : "+f"((c)[0]), "+f"((c)[1]), "+f"((c)[2]), "+f"((c)[3]) \
                 : "r"((a)[0]), "r"((a)[1]), "r"((a)[2]), "r"((a)[3]), \
                   "r"((b)[0]), "r"((b)[1]))

#define LDSM4(r0, r1, r2, r3, addr) \
    asm volatile("ldmatrix.sync.aligned.m8n8.x4.shared.b16 {%0,%1,%2,%3}, [%4];" \
                 : "=r"(r0), "=r"(r1), "=r"(r2), "=r"(r3) : "r"(addr))

__device__ __forceinline__ uint32_t pack2(__nv_bfloat16 a, __nv_bfloat16 b) {
    return (uint32_t)__bfloat16_as_ushort(a) | ((uint32_t)__bfloat16_as_ushort(b) << 16);
}

// ---------------- prep ----------------
__global__ void k_split_zero(const float* __restrict__ W1) {
    int i = blockIdx.x * 256 + threadIdx.x;
    if (i < MAXN) g_cnt[i] = 0;
    if (i < F_IN * HID) {
        int k = i >> 8, n = i & 255;
        float w = W1[(size_t)k * HID + n];
        __nv_bfloat16 hi = __float2bfloat16_rn(w);
        __nv_bfloat16 lo = __float2bfloat16_rn(w - __bfloat162float(hi));
        g_w1hi[(size_t)n * F_IN + k] = hi;
        g_w1lo[(size_t)n * F_IN + k] = lo;
    }
}

__global__ void k_count(const int* __restrict__ ei, int E) {
    int e = blockIdx.x * 256 + threadIdx.x;
    if (e >= E) return;
    atomicAdd(&g_cnt[ei[E + e]], 1);
}

__global__ void k_scan1(int M) {
    __shared__ int sd[1024];
    int t = threadIdx.x, b = blockIdx.x;
    int i = b * 1024 + t;
    int v = (i < M) ? g_cnt[i] : 0;
    sd[t] = v;
    __syncthreads();
    for (int off = 1; off < 1024; off <<= 1) {
        int x = (t >= off) ? sd[t - off] : 0;
        __syncthreads();
        sd[t] += x;
        __syncthreads();
    }
    if (i < M) g_rowstart[i] = sd[t] - v;
    if (t == 1023) g_bsum[b] = sd[1023];
}

__global__ void k_scan2(int nb) {
    __shared__ int sd[128];
    int t = threadIdx.x;
    int v = (t < nb) ? g_bsum[t] : 0;
    sd[t] = v;
    __syncthreads();
    for (int off = 1; off < 128; off <<= 1) {
        int x = (t >= off) ? sd[t - off] : 0;
        __syncthreads();
        sd[t] += x;
        __syncthreads();
    }
    if (t < nb) g_bsum[t] = sd[t] - v;
}

__global__ void k_scan3(int M, int E) {
    int i = blockIdx.x * 256 + threadIdx.x;
    if (i >= M) return;
    int rs = g_rowstart[i] + g_bsum[i >> 10];
    g_rowstart[i] = rs;
    g_cursor[i] = rs;
    g_dinv[i] = rsqrtf((float)g_cnt[i] + 1.0f);
    if (i == 0) g_rowstart[M] = E;
}

__global__ void k_bucket(const int* __restrict__ ei, int E) {
    int e = blockIdx.x * 256 + threadIdx.x;
    if (e >= E) return;
    int s = ei[e], d = ei[E + e];
    int pos = atomicAdd(&g_cursor[d], 1);
    g_se[pos] = s;
    g_ce[pos] = g_dinv[s] * g_dinv[d];
}

// ---------------- GEMM1: bf16x3 mma + ldmatrix fragments ----------------
// smem rows pack [hi(32) | lo(32)] bf16, stride 72 elems (144B -> conflict-free ldmatrix)
#define ASTR2 72
__global__ void __launch_bounds__(256) k_gemm1(const float* __restrict__ A, int M) {
    __shared__ __nv_bfloat16 Asm[128 * ASTR2];
    __shared__ __nv_bfloat16 Bsm[128 * ASTR2];
    int tid = threadIdx.x, lane = tid & 31, wid = tid >> 5;
    int bm = blockIdx.y * 128, bn = blockIdx.x * 128;
    int m0 = (wid & 1) * 64, n0 = (wid >> 1) * 32;

    // ldmatrix lane->address bases (bytes)
    uint32_t aBase0 = (uint32_t)__cvta_generic_to_shared(Asm) +
                      (uint32_t)(((m0 + (lane & 15)) * ASTR2 + (lane >> 4) * 8) * 2);
    uint32_t bBase0 = (uint32_t)__cvta_generic_to_shared(Bsm) +
                      (uint32_t)(((n0 + (lane & 7)) * ASTR2 +
                                  ((lane >> 3) & 1) * 8 + (lane >> 4) * 32) * 2);

    float c[4][4][4];
#pragma unroll
    for (int i = 0; i < 4; i++)
#pragma unroll
        for (int j = 0; j < 4; j++)
#pragma unroll
            for (int r = 0; r < 4; r++) c[i][j][r] = 0.0f;

    for (int s = 0; s < F_IN / 32; s++) {
        int k0 = s * 32;
        // A loader: 128 rows x 32 k fp32 -> bf16 hi/lo packed per row (1024 chunks)
#pragma unroll
        for (int i = 0; i < 4; i++) {
            int ch = tid + i * 256;          // 0..1023
            int m = ch >> 3, k4 = ch & 7;
            float4 a = make_float4(0.f, 0.f, 0.f, 0.f);
            if (bm + m < M)
                a = *(const float4*)(A + (size_t)(bm + m) * F_IN + k0 + k4 * 4);
            __nv_bfloat16 hx = __float2bfloat16_rn(a.x), hy = __float2bfloat16_rn(a.y);
            __nv_bfloat16 hz = __float2bfloat16_rn(a.z), hw = __float2bfloat16_rn(a.w);
            __nv_bfloat16 lx = __float2bfloat16_rn(a.x - __bfloat162float(hx));
            __nv_bfloat16 ly = __float2bfloat16_rn(a.y - __bfloat162float(hy));
            __nv_bfloat16 lz = __float2bfloat16_rn(a.z - __bfloat162float(hz));
            __nv_bfloat16 lw = __float2bfloat16_rn(a.w - __bfloat162float(hw));
            *(uint2*)&Asm[m * ASTR2 + k4 * 4]      = make_uint2(pack2(hx, hy), pack2(hz, hw));
            *(uint2*)&Asm[m * ASTR2 + 32 + k4 * 4] = make_uint2(pack2(lx, ly), pack2(lz, lw));
        }
        // B loader: 128 rows x (32 hi + 32 lo) = 8 uint4 chunks/row = 1024 chunks
#pragma unroll
        for (int i = 0; i < 4; i++) {
            int ch = tid + i * 256;          // 0..1023
            int n = ch >> 3, q = ch & 7;
            if (q < 4)
                *(uint4*)&Bsm[n * ASTR2 + q * 8] =
                    *(const uint4*)(g_w1hi + (size_t)(bn + n) * F_IN + k0 + q * 8);
            else
                *(uint4*)&Bsm[n * ASTR2 + 32 + (q - 4) * 8] =
                    *(const uint4*)(g_w1lo + (size_t)(bn + n) * F_IN + k0 + (q - 4) * 8);
        }
        __syncthreads();

#pragma unroll
        for (int kk = 0; kk < 32; kk += 16) {
            uint32_t ah[4][4], al[4][4], bh[4][2], bl[4][2];
#pragma unroll
            for (int tm = 0; tm < 4; tm++) {
                uint32_t aa = aBase0 + (uint32_t)(tm * 16 * ASTR2 * 2 + kk * 2);
                LDSM4(ah[tm][0], ah[tm][1], ah[tm][2], ah[tm][3], aa);
                LDSM4(al[tm][0], al[tm][1], al[tm][2], al[tm][3], aa + 64);
            }
#pragma unroll
            for (int tn = 0; tn < 4; tn++) {
                uint32_t bb = bBase0 + (uint32_t)(tn * 8 * ASTR2 * 2 + kk * 2);
                LDSM4(bh[tn][0], bh[tn][1], bl[tn][0], bl[tn][1], bb);
            }
#pragma unroll
            for (int tm = 0; tm < 4; tm++)
#pragma unroll
                for (int tn = 0; tn < 4; tn++) {
                    MMA_BF16(c[tm][tn], ah[tm], bh[tn]);
                    MMA_BF16(c[tm][tn], ah[tm], bl[tn]);
                    MMA_BF16(c[tm][tn], al[tm], bh[tn]);
                }
        }
        __syncthreads();
    }

#pragma unroll
    for (int tm = 0; tm < 4; tm++) {
        int row0 = bm + m0 + tm * 16 + (lane >> 2);
#pragma unroll
        for (int h = 0; h < 2; h++) {
            int row = row0 + h * 8;
            if (row >= M) continue;
#pragma unroll
            for (int tn = 0; tn < 4; tn++) {
                int col = bn + n0 + tn * 8 + (lane & 3) * 2;
                *(float2*)(g_h1 + (size_t)row * HID + col) =
                    make_float2(c[tm][tn][h * 2 + 0], c[tm][tn][h * 2 + 1]);
            }
        }
    }
}

// ---------------- agg layer 1: block per dst node, unroll 4, no atomics ----------------
__global__ void __launch_bounds__(256) k_agg1(int M) {
    int n = blockIdx.x;
    int tid = threadIdx.x;
    int st = g_rowstart[n], en = g_rowstart[n + 1];
    float dv = g_dinv[n];
    float acc = g_h1[(size_t)n * HID + tid] * (dv * dv);
    int e = st;
    for (; e + 3 < en; e += 4) {
        int s0 = g_se[e], s1 = g_se[e + 1], s2 = g_se[e + 2], s3 = g_se[e + 3];
        float c0 = g_ce[e], c1 = g_ce[e + 1], c2 = g_ce[e + 2], c3 = g_ce[e + 3];
        float v0 = __ldg(g_h1 + (size_t)s0 * HID + tid);
        float v1 = __ldg(g_h1 + (size_t)s1 * HID + tid);
        float v2 = __ldg(g_h1 + (size_t)s2 * HID + tid);
        float v3 = __ldg(g_h1 + (size_t)s3 * HID + tid);
        acc += v0 * c0 + v1 * c1 + v2 * c2 + v3 * c3;
    }
    for (; e < en; e++)
        acc += __ldg(g_h1 + (size_t)g_se[e] * HID + tid) * g_ce[e];
    g_agg1[(size_t)n * HID + tid] = acc;
}

// ---------------- GEMM2 (bias+relu fused A-loader) ----------------
__global__ void __launch_bounds__(256) k_gemm2(const float* __restrict__ W2,
                                               const float* __restrict__ b1, int M) {
    __shared__ float As[32][128];
    __shared__ float Ws[32][NCLS];
    int tid = threadIdx.x;
    int tx = tid & 7, ty = tid >> 3;
    int bm = blockIdx.x * 128;

    float acc[4][5];
#pragma unroll
    for (int i = 0; i < 4; i++)
#pragma unroll
        for (int j = 0; j < 5; j++) acc[i][j] = 0.0f;

    for (int k0 = 0; k0 < HID; k0 += 32) {
#pragma unroll
        for (int i = 0; i < 4; i++) {
            int lin = tid + i * 256;
            int r = lin >> 3, c4 = lin & 7;
            int row = bm + r;
            float4 a4 = make_float4(0.f, 0.f, 0.f, 0.f);
            if (row < M) {
                a4 = *(const float4*)(g_agg1 + (size_t)row * HID + k0 + c4 * 4);
                float4 bb = *(const float4*)(b1 + k0 + c4 * 4);
                a4.x = fmaxf(a4.x + bb.x, 0.0f);
                a4.y = fmaxf(a4.y + bb.y, 0.0f);
                a4.z = fmaxf(a4.z + bb.z, 0.0f);
                a4.w = fmaxf(a4.w + bb.w, 0.0f);
            }
            As[c4 * 4 + 0][r] = a4.x;
            As[c4 * 4 + 1][r] = a4.y;
            As[c4 * 4 + 2][r] = a4.z;
            As[c4 * 4 + 3][r] = a4.w;
        }
#pragma unroll
        for (int i = 0; i < 5; i++) {
            int lin = tid + i * 256;
            int r = lin / NCLS, c = lin % NCLS;
            Ws[r][c] = W2[(size_t)(k0 + r) * NCLS + c];
        }
        __syncthreads();

#pragma unroll
        for (int kk = 0; kk < 32; kk++) {
            float4 a = *(float4*)&As[kk][ty * 4];
            float av[4] = {a.x, a.y, a.z, a.w};
            float w[5];
#pragma unroll
            for (int j = 0; j < 5; j++) w[j] = Ws[kk][tx * 5 + j];
#pragma unroll
            for (int i = 0; i < 4; i++)
#pragma unroll
                for (int j = 0; j < 5; j++)
                    acc[i][j] = fmaf(av[i], w[j], acc[i][j]);
        }
        __syncthreads();
    }

#pragma unroll
    for (int i = 0; i < 4; i++) {
        int row = bm + ty * 4 + i;
        if (row >= M) continue;
#pragma unroll
        for (int j = 0; j < 5; j++)
            g_h2[(size_t)row * NCLS + tx * 5 + j] = acc[i][j];
    }
}

// ---------------- fused agg layer 2 + bias + log_softmax/softmax ----------------
__global__ void __launch_bounds__(256) k_agg2soft(const float* __restrict__ b2,
                                                  float* __restrict__ out,
                                                  int M, int write_soft) {
    int warp = threadIdx.x >> 5, lane = threadIdx.x & 31;
    int n = blockIdx.x * 8 + warp;
    if (n >= M) return;
    int st = g_rowstart[n], en = g_rowstart[n + 1];
    float dv = g_dinv[n];
    float d2 = dv * dv;
    bool has1 = lane < (NCLS - 32);
    const float* hn = g_h2 + (size_t)n * NCLS;
    float a0 = hn[lane] * d2;
    float a1 = has1 ? hn[32 + lane] * d2 : 0.0f;
    for (int e = st; e < en; e++) {
        int s = g_se[e];
        float cc = g_ce[e];
        const float* hs = g_h2 + (size_t)s * NCLS;
        a0 += hs[lane] * cc;
        if (has1) a1 += hs[32 + lane] * cc;
    }
    float v0 = a0 + b2[lane];
    float v1 = has1 ? (a1 + b2[32 + lane]) : -INFINITY;
    float m = fmaxf(v0, v1);
#pragma unroll
    for (int o = 16; o; o >>= 1) m = fmaxf(m, __shfl_xor_sync(0xffffffffu, m, o));
    float s = expf(v0 - m) + (has1 ? expf(v1 - m) : 0.0f);
#pragma unroll
    for (int o = 16; o; o >>= 1) s += __shfl_xor_sync(0xffffffffu, s, o);
    float lse = m + logf(s);
    float l0 = v0 - lse;
    out[(size_t)n * NCLS + lane] = l0;
    if (write_soft) out[(size_t)M * NCLS + (size_t)n * NCLS + lane] = expf(l0);
    if (has1) {
        float l1 = v1 - lse;
        out[(size_t)n * NCLS + lane + 32] = l1;
        if (write_soft) out[(size_t)M * NCLS + (size_t)n * NCLS + lane + 32] = expf(l1);
    }
}

extern "C" void kernel_launch(void* const* d_in, const int* in_sizes, int n_in,
                              void* d_out, int out_size) {
    const float* features = (const float*)d_in[0];
    const float* W1       = (const float*)d_in[1];
    const float* b1       = (const float*)d_in[2];
    const float* W2       = (const float*)d_in[3];
    const float* b2       = (const float*)d_in[4];
    const int*   ei       = (const int*)d_in[5];

    int M = in_sizes[0] / F_IN;
    int E = in_sizes[5] / 2;
    float* out = (float*)d_out;
    int write_soft = (out_size >= 2 * M * NCLS) ? 1 : 0;
    int nb = (M + 1023) / 1024;

    k_split_zero<<<(F_IN * HID + 255) / 256, 256>>>(W1);       // 1
    k_count<<<(E + 255) / 256, 256>>>(ei, E);                  // 2
    k_scan1<<<nb, 1024>>>(M);                                  // 3

    dim3 g1(HID / 128, (M + 127) / 128);
    k_gemm1<<<g1, 256>>>(features, M);                         // 4  <- profiled

    k_scan2<<<1, 128>>>(nb);                                   // 5
    k_scan3<<<(M + 255) / 256, 256>>>(M, E);                   // 6
    k_bucket<<<(E + 255) / 256, 256>>>(ei, E);                 // 7
    k_agg1<<<M, 256>>>(M);                                     // 8
    k_gemm2<<<(M + 127) / 128, 256>>>(W2, b1, M);              // 9
    k_agg2soft<<<(M + 7) / 8, 256>>>(b2, out, M, write_soft);  // 10
}

// round 13
// speedup vs baseline: 1.1718x; 1.1718x over previous
#include <cuda_runtime.h>
#include <cuda_bf16.h>
#include <math.h>
#include <stdint.h>

#define F_IN 512
#define HID  256
#define NCLS 40
#define MAXN 100000
#define MAXE 1600000

// ---- scratch ----
__device__ float g_h1  [(size_t)MAXN * HID];
__device__ float g_agg1[(size_t)MAXN * HID];
__device__ float g_h2  [(size_t)MAXN * NCLS];
__device__ float g_dinv[MAXN];
__device__ int   g_cnt [MAXN];
__device__ int   g_rowstart[MAXN + 1];
__device__ int   g_cursor[MAXN];
__device__ int   g_se[MAXE];
__device__ float g_ce[MAXE];
__device__ int   g_bsum[128];
__device__ __nv_bfloat16 g_w1hi[(size_t)HID * F_IN];   // [n][k] transposed
__device__ __nv_bfloat16 g_w1lo[(size_t)HID * F_IN];

#define MMA_BF16(c, a, b) \
    asm volatile("mma.sync.aligned.m16n8k16.row.col.f32.bf16.bf16.f32 " \
                 "{%0,%1,%2,%3}, {%4,%5,%6,%7}, {%8,%9}, {%0,%1,%2,%3};" \
                 : "+f"((c)[0]), "+f"((c)[1]), "+f"((c)[2]), "+f"((c)[3]) \
                 : "r"((a)[0]), "r"((a)[1]), "r"((a)[2]), "r"((a)[3]), \
                   "r"((b)[0]), "r"((b)[1]))

#define LDSM4(r0, r1, r2, r3, addr) \
    asm volatile("ldmatrix.sync.aligned.m8n8.x4.shared.b16 {%0,%1,%2,%3}, [%4];" \
                 : "=r"(r0), "=r"(r1), "=r"(r2), "=r"(r3) : "r"(addr))

__device__ __forceinline__ uint32_t pack2(__nv_bfloat16 a, __nv_bfloat16 b) {
    return (uint32_t)__bfloat16_as_ushort(a) | ((uint32_t)__bfloat16_as_ushort(b) << 16);
}

// ---------------- prep ----------------
__global__ void k_split_zero(const float* __restrict__ W1) {
    int i = blockIdx.x * 256 + threadIdx.x;
    if (i < MAXN) g_cnt[i] = 0;
    if (i < F_IN * HID) {
        int k = i >> 8, n = i & 255;
        float w = W1[(size_t)k * HID + n];
        __nv_bfloat16 hi = __float2bfloat16_rn(w);
        __nv_bfloat16 lo = __float2bfloat16_rn(w - __bfloat162float(hi));
        g_w1hi[(size_t)n * F_IN + k] = hi;
        g_w1lo[(size_t)n * F_IN + k] = lo;
    }
}

__global__ void k_count(const int* __restrict__ ei, int E) {
    int e = blockIdx.x * 256 + threadIdx.x;
    if (e >= E) return;
    atomicAdd(&g_cnt[ei[E + e]], 1);
}

__global__ void k_scan1(int M) {
    __shared__ int sd[1024];
    int t = threadIdx.x, b = blockIdx.x;
    int i = b * 1024 + t;
    int v = (i < M) ? g_cnt[i] : 0;
    sd[t] = v;
    __syncthreads();
    for (int off = 1; off < 1024; off <<= 1) {
        int x = (t >= off) ? sd[t - off] : 0;
        __syncthreads();
        sd[t] += x;
        __syncthreads();
    }
    if (i < M) g_rowstart[i] = sd[t] - v;
    if (t == 1023) g_bsum[b] = sd[1023];
}

__global__ void k_scan2(int nb) {
    __shared__ int sd[128];
    int t = threadIdx.x;
    int v = (t < nb) ? g_bsum[t] : 0;
    sd[t] = v;
    __syncthreads();
    for (int off = 1; off < 128; off <<= 1) {
        int x = (t >= off) ? sd[t - off] : 0;
        __syncthreads();
        sd[t] += x;
        __syncthreads();
    }
    if (t < nb) g_bsum[t] = sd[t] - v;
}

__global__ void k_scan3(int M, int E) {
    int i = blockIdx.x * 256 + threadIdx.x;
    if (i >= M) return;
    int rs = g_rowstart[i] + g_bsum[i >> 10];
    g_rowstart[i] = rs;
    g_cursor[i] = rs;
    g_dinv[i] = rsqrtf((float)g_cnt[i] + 1.0f);
    if (i == 0) g_rowstart[M] = E;
}

__global__ void k_bucket(const int* __restrict__ ei, int E) {
    int e = blockIdx.x * 256 + threadIdx.x;
    if (e >= E) return;
    int s = ei[e], d = ei[E + e];
    int pos = atomicAdd(&g_cursor[d], 1);
    g_se[pos] = s;
    g_ce[pos] = g_dinv[s] * g_dinv[d];
}

// ---------------- GEMM1: bf16x3 mma + ldmatrix, reg-capped for 2 CTA/SM ----------------
// smem rows pack [hi(32) | lo(32)] bf16, stride 72 elems (144B -> conflict-free ldmatrix)
#define ASTR2 72
__global__ void __launch_bounds__(256, 2) k_gemm1(const float* __restrict__ A, int M) {
    __shared__ __nv_bfloat16 Asm[128 * ASTR2];
    __shared__ __nv_bfloat16 Bsm[128 * ASTR2];
    int tid = threadIdx.x, lane = tid & 31, wid = tid >> 5;
    int bm = blockIdx.y * 128, bn = blockIdx.x * 128;
    int m0 = (wid & 1) * 64, n0 = (wid >> 1) * 32;

    // ldmatrix lane->address bases (bytes)
    uint32_t aBase0 = (uint32_t)__cvta_generic_to_shared(Asm) +
                      (uint32_t)(((m0 + (lane & 15)) * ASTR2 + (lane >> 4) * 8) * 2);
    uint32_t bBase0 = (uint32_t)__cvta_generic_to_shared(Bsm) +
                      (uint32_t)(((n0 + (lane & 7)) * ASTR2 +
                                  ((lane >> 3) & 1) * 8 + (lane >> 4) * 32) * 2);

    float c[4][4][4];
#pragma unroll
    for (int i = 0; i < 4; i++)
#pragma unroll
        for (int j = 0; j < 4; j++)
#pragma unroll
            for (int r = 0; r < 4; r++) c[i][j][r] = 0.0f;

    for (int s = 0; s < F_IN / 32; s++) {
        int k0 = s * 32;
        // A loader: 128 rows x 32 k fp32 -> bf16 hi/lo packed per row (1024 chunks)
#pragma unroll
        for (int i = 0; i < 4; i++) {
            int ch = tid + i * 256;          // 0..1023
            int m = ch >> 3, k4 = ch & 7;
            float4 a = make_float4(0.f, 0.f, 0.f, 0.f);
            if (bm + m < M)
                a = *(const float4*)(A + (size_t)(bm + m) * F_IN + k0 + k4 * 4);
            __nv_bfloat16 hx = __float2bfloat16_rn(a.x), hy = __float2bfloat16_rn(a.y);
            __nv_bfloat16 hz = __float2bfloat16_rn(a.z), hw = __float2bfloat16_rn(a.w);
            __nv_bfloat16 lx = __float2bfloat16_rn(a.x - __bfloat162float(hx));
            __nv_bfloat16 ly = __float2bfloat16_rn(a.y - __bfloat162float(hy));
            __nv_bfloat16 lz = __float2bfloat16_rn(a.z - __bfloat162float(hz));
            __nv_bfloat16 lw = __float2bfloat16_rn(a.w - __bfloat162float(hw));
            *(uint2*)&Asm[m * ASTR2 + k4 * 4]      = make_uint2(pack2(hx, hy), pack2(hz, hw));
            *(uint2*)&Asm[m * ASTR2 + 32 + k4 * 4] = make_uint2(pack2(lx, ly), pack2(lz, lw));
        }
        // B loader: 128 rows x (32 hi + 32 lo) = 8 uint4 chunks/row = 1024 chunks
#pragma unroll
        for (int i = 0; i < 4; i++) {
            int ch = tid + i * 256;          // 0..1023
            int n = ch >> 3, q = ch & 7;
            if (q < 4)
                *(uint4*)&Bsm[n * ASTR2 + q * 8] =
                    *(const uint4*)(g_w1hi + (size_t)(bn + n) * F_IN + k0 + q * 8);
            else
                *(uint4*)&Bsm[n * ASTR2 + 32 + (q - 4) * 8] =
                    *(const uint4*)(g_w1lo + (size_t)(bn + n) * F_IN + k0 + (q - 4) * 8);
        }
        __syncthreads();

#pragma unroll
        for (int kk = 0; kk < 32; kk += 16) {
            uint32_t ah[4][4], al[4][4], bh[4][2], bl[4][2];
#pragma unroll
            for (int tm = 0; tm < 4; tm++) {
                uint32_t aa = aBase0 + (uint32_t)(tm * 16 * ASTR2 * 2 + kk * 2);
                LDSM4(ah[tm][0], ah[tm][1], ah[tm][2], ah[tm][3], aa);
                LDSM4(al[tm][0], al[tm][1], al[tm][2], al[tm][3], aa + 64);
            }
#pragma unroll
            for (int tn = 0; tn < 4; tn++) {
                uint32_t bb = bBase0 + (uint32_t)(tn * 8 * ASTR2 * 2 + kk * 2);
                LDSM4(bh[tn][0], bh[tn][1], bl[tn][0], bl[tn][1], bb);
            }
#pragma unroll
            for (int tm = 0; tm < 4; tm++)
#pragma unroll
                for (int tn = 0; tn < 4; tn++) {
                    MMA_BF16(c[tm][tn], ah[tm], bh[tn]);
                    MMA_BF16(c[tm][tn], ah[tm], bl[tn]);
                    MMA_BF16(c[tm][tn], al[tm], bh[tn]);
                }
        }
        __syncthreads();
    }

#pragma unroll
    for (int tm = 0; tm < 4; tm++) {
        int row0 = bm + m0 + tm * 16 + (lane >> 2);
#pragma unroll
        for (int h = 0; h < 2; h++) {
            int row = row0 + h * 8;
            if (row >= M) continue;
#pragma unroll
            for (int tn = 0; tn < 4; tn++) {
                int col = bn + n0 + tn * 8 + (lane & 3) * 2;
                *(float2*)(g_h1 + (size_t)row * HID + col) =
                    make_float2(c[tm][tn][h * 2 + 0], c[tm][tn][h * 2 + 1]);
            }
        }
    }
}

// ---------------- agg layer 1: block per dst node, unroll 4, no atomics ----------------
__global__ void __launch_bounds__(256) k_agg1(int M) {
    int n = blockIdx.x;
    int tid = threadIdx.x;
    int st = g_rowstart[n], en = g_rowstart[n + 1];
    float dv = g_dinv[n];
    float acc = g_h1[(size_t)n * HID + tid] * (dv * dv);
    int e = st;
    for (; e + 3 < en; e += 4) {
        int s0 = g_se[e], s1 = g_se[e + 1], s2 = g_se[e + 2], s3 = g_se[e + 3];
        float c0 = g_ce[e], c1 = g_ce[e + 1], c2 = g_ce[e + 2], c3 = g_ce[e + 3];
        float v0 = __ldg(g_h1 + (size_t)s0 * HID + tid);
        float v1 = __ldg(g_h1 + (size_t)s1 * HID + tid);
        float v2 = __ldg(g_h1 + (size_t)s2 * HID + tid);
        float v3 = __ldg(g_h1 + (size_t)s3 * HID + tid);
        acc += v0 * c0 + v1 * c1 + v2 * c2 + v3 * c3;
    }
    for (; e < en; e++)
        acc += __ldg(g_h1 + (size_t)g_se[e] * HID + tid) * g_ce[e];
    g_agg1[(size_t)n * HID + tid] = acc;
}

// ---------------- GEMM2 (bias+relu fused A-loader) ----------------
__global__ void __launch_bounds__(256) k_gemm2(const float* __restrict__ W2,
                                               const float* __restrict__ b1, int M) {
    __shared__ float As[32][128];
    __shared__ float Ws[32][NCLS];
    int tid = threadIdx.x;
    int tx = tid & 7, ty = tid >> 3;
    int bm = blockIdx.x * 128;

    float acc[4][5];
#pragma unroll
    for (int i = 0; i < 4; i++)
#pragma unroll
        for (int j = 0; j < 5; j++) acc[i][j] = 0.0f;

    for (int k0 = 0; k0 < HID; k0 += 32) {
#pragma unroll
        for (int i = 0; i < 4; i++) {
            int lin = tid + i * 256;
            int r = lin >> 3, c4 = lin & 7;
            int row = bm + r;
            float4 a4 = make_float4(0.f, 0.f, 0.f, 0.f);
            if (row < M) {
                a4 = *(const float4*)(g_agg1 + (size_t)row * HID + k0 + c4 * 4);
                float4 bb = *(const float4*)(b1 + k0 + c4 * 4);
                a4.x = fmaxf(a4.x + bb.x, 0.0f);
                a4.y = fmaxf(a4.y + bb.y, 0.0f);
                a4.z = fmaxf(a4.z + bb.z, 0.0f);
                a4.w = fmaxf(a4.w + bb.w, 0.0f);
            }
            As[c4 * 4 + 0][r] = a4.x;
            As[c4 * 4 + 1][r] = a4.y;
            As[c4 * 4 + 2][r] = a4.z;
            As[c4 * 4 + 3][r] = a4.w;
        }
#pragma unroll
        for (int i = 0; i < 5; i++) {
            int lin = tid + i * 256;
            int r = lin / NCLS, c = lin % NCLS;
            Ws[r][c] = W2[(size_t)(k0 + r) * NCLS + c];
        }
        __syncthreads();

#pragma unroll
        for (int kk = 0; kk < 32; kk++) {
            float4 a = *(float4*)&As[kk][ty * 4];
            float av[4] = {a.x, a.y, a.z, a.w};
            float w[5];
#pragma unroll
            for (int j = 0; j < 5; j++) w[j] = Ws[kk][tx * 5 + j];
#pragma unroll
            for (int i = 0; i < 4; i++)
#pragma unroll
                for (int j = 0; j < 5; j++)
                    acc[i][j] = fmaf(av[i], w[j], acc[i][j]);
        }
        __syncthreads();
    }

#pragma unroll
    for (int i = 0; i < 4; i++) {
        int row = bm + ty * 4 + i;
        if (row >= M) continue;
#pragma unroll
        for (int j = 0; j < 5; j++)
            g_h2[(size_t)row * NCLS + tx * 5 + j] = acc[i][j];
    }
}

// ---------------- fused agg layer 2 + bias + log_softmax/softmax ----------------
__global__ void __launch_bounds__(256) k_agg2soft(const float* __restrict__ b2,
                                                  float* __restrict__ out,
                                                  int M, int write_soft) {
    int warp = threadIdx.x >> 5, lane = threadIdx.x & 31;
    int n = blockIdx.x * 8 + warp;
    if (n >= M) return;
    int st = g_rowstart[n], en = g_rowstart[n + 1];
    float dv = g_dinv[n];
    float d2 = dv * dv;
    bool has1 = lane < (NCLS - 32);
    const float* hn = g_h2 + (size_t)n * NCLS;
    float a0 = hn[lane] * d2;
    float a1 = has1 ? hn[32 + lane] * d2 : 0.0f;
    for (int e = st; e < en; e++) {
        int s = g_se[e];
        float cc = g_ce[e];
        const float* hs = g_h2 + (size_t)s * NCLS;
        a0 += hs[lane] * cc;
        if (has1) a1 += hs[32 + lane] * cc;
    }
    float v0 = a0 + b2[lane];
    float v1 = has1 ? (a1 + b2[32 + lane]) : -INFINITY;
    float m = fmaxf(v0, v1);
#pragma unroll
    for (int o = 16; o; o >>= 1) m = fmaxf(m, __shfl_xor_sync(0xffffffffu, m, o));
    float s = expf(v0 - m) + (has1 ? expf(v1 - m) : 0.0f);
#pragma unroll
    for (int o = 16; o; o >>= 1) s += __shfl_xor_sync(0xffffffffu, s, o);
    float lse = m + logf(s);
    float l0 = v0 - lse;
    out[(size_t)n * NCLS + lane] = l0;
    if (write_soft) out[(size_t)M * NCLS + (size_t)n * NCLS + lane] = expf(l0);
    if (has1) {
        float l1 = v1 - lse;
        out[(size_t)n * NCLS + lane + 32] = l1;
        if (write_soft) out[(size_t)M * NCLS + (size_t)n * NCLS + lane + 32] = expf(l1);
    }
}

extern "C" void kernel_launch(void* const* d_in, const int* in_sizes, int n_in,
                              void* d_out, int out_size) {
    const float* features = (const float*)d_in[0];
    const float* W1       = (const float*)d_in[1];
    const float* b1       = (const float*)d_in[2];
    const float* W2       = (const float*)d_in[3];
    const float* b2       = (const float*)d_in[4];
    const int*   ei       = (const int*)d_in[5];

    int M = in_sizes[0] / F_IN;
    int E = in_sizes[5] / 2;
    float* out = (float*)d_out;
    int write_soft = (out_size >= 2 * M * NCLS) ? 1 : 0;
    int nb = (M + 1023) / 1024;

    k_split_zero<<<(F_IN * HID + 255) / 256, 256>>>(W1);       // 1
    k_count<<<(E + 255) / 256, 256>>>(ei, E);                  // 2
    k_scan1<<<nb, 1024>>>(M);                                  // 3

    dim3 g1(HID / 128, (M + 127) / 128);
    k_gemm1<<<g1, 256>>>(features, M);                         // 4  <- profiled

    k_scan2<<<1, 128>>>(nb);                                   // 5
    k_scan3<<<(M + 255) / 256, 256>>>(M, E);                   // 6
    k_bucket<<<(E + 255) / 256, 256>>>(ei, E);                 // 7
    k_agg1<<<M, 256>>>(M);                                     // 8
    k_gemm2<<<(M + 127) / 128, 256>>>(W2, b1, M);              // 9
    k_agg2soft<<<(M + 7) / 8, 256>>>(b2, out, M, write_soft);  // 10
}

// round 14
// speedup vs baseline: 1.2205x; 1.0416x over previous
#include <cuda_runtime.h>
#include <cuda_bf16.h>
#include <math.h>
#include <stdint.h>

#define F_IN 512
#define HID  256
#define NCLS 40
#define MAXN 100000
#define MAXE 1600000

// ---- scratch ----
__device__ float g_h1  [(size_t)MAXN * HID];
__device__ float g_agg1[(size_t)MAXN * HID];
__device__ float g_h2  [(size_t)MAXN * NCLS];
__device__ float g_dinv[MAXN];
__device__ int   g_cnt [MAXN];
__device__ int   g_rowstart[MAXN + 1];
__device__ int   g_cursor[MAXN];
__device__ int   g_se[MAXE];
__device__ float g_ce[MAXE];
__device__ int   g_bsum[128];
__device__ __nv_bfloat16 g_w1hi[(size_t)HID * F_IN];   // [n][k] transposed
__device__ __nv_bfloat16 g_w1lo[(size_t)HID * F_IN];

#define MMA_BF16(c, a, b) \
    asm volatile("mma.sync.aligned.m16n8k16.row.col.f32.bf16.bf16.f32 " \
                 "{%0,%1,%2,%3}, {%4,%5,%6,%7}, {%8,%9}, {%0,%1,%2,%3};" \
                 : "+f"((c)[0]), "+f"((c)[1]), "+f"((c)[2]), "+f"((c)[3]) \
                 : "r"((a)[0]), "r"((a)[1]), "r"((a)[2]), "r"((a)[3]), \
                   "r"((b)[0]), "r"((b)[1]))

#define LDSM4(r0, r1, r2, r3, addr) \
    asm volatile("ldmatrix.sync.aligned.m8n8.x4.shared.b16 {%0,%1,%2,%3}, [%4];" \
                 : "=r"(r0), "=r"(r1), "=r"(r2), "=r"(r3) : "r"(addr))

__device__ __forceinline__ uint32_t pack2(__nv_bfloat16 a, __nv_bfloat16 b) {
    return (uint32_t)__bfloat16_as_ushort(a) | ((uint32_t)__bfloat16_as_ushort(b) << 16);
}

// ---------------- prep ----------------
__global__ void k_split_zero(const float* __restrict__ W1) {
    int i = blockIdx.x * 256 + threadIdx.x;
    if (i < MAXN) g_cnt[i] = 0;
    if (i < F_IN * HID) {
        int k = i >> 8, n = i & 255;
        float w = W1[(size_t)k * HID + n];
        __nv_bfloat16 hi = __float2bfloat16_rn(w);
        __nv_bfloat16 lo = __float2bfloat16_rn(w - __bfloat162float(hi));
        g_w1hi[(size_t)n * F_IN + k] = hi;
        g_w1lo[(size_t)n * F_IN + k] = lo;
    }
}

__global__ void k_count(const int* __restrict__ ei, int E) {
    int e = blockIdx.x * 256 + threadIdx.x;
    if (e >= E) return;
    atomicAdd(&g_cnt[ei[E + e]], 1);
}

__global__ void k_scan1(int M) {
    __shared__ int sd[1024];
    int t = threadIdx.x, b = blockIdx.x;
    int i = b * 1024 + t;
    int v = (i < M) ? g_cnt[i] : 0;
    sd[t] = v;
    __syncthreads();
    for (int off = 1; off < 1024; off <<= 1) {
        int x = (t >= off) ? sd[t - off] : 0;
        __syncthreads();
        sd[t] += x;
        __syncthreads();
    }
    if (i < M) g_rowstart[i] = sd[t] - v;
    if (t == 1023) g_bsum[b] = sd[1023];
}

__global__ void k_scan2(int nb) {
    __shared__ int sd[128];
    int t = threadIdx.x;
    int v = (t < nb) ? g_bsum[t] : 0;
    sd[t] = v;
    __syncthreads();
    for (int off = 1; off < 128; off <<= 1) {
        int x = (t >= off) ? sd[t - off] : 0;
        __syncthreads();
        sd[t] += x;
        __syncthreads();
    }
    if (t < nb) g_bsum[t] = sd[t] - v;
}

__global__ void k_scan3(int M, int E) {
    int i = blockIdx.x * 256 + threadIdx.x;
    if (i >= M) return;
    int rs = g_rowstart[i] + g_bsum[i >> 10];
    g_rowstart[i] = rs;
    g_cursor[i] = rs;
    g_dinv[i] = rsqrtf((float)g_cnt[i] + 1.0f);
    if (i == 0) g_rowstart[M] = E;
}

__global__ void k_bucket(const int* __restrict__ ei, int E) {
    int e = blockIdx.x * 256 + threadIdx.x;
    if (e >= E) return;
    int s = ei[e], d = ei[E + e];
    int pos = atomicAdd(&g_cursor[d], 1);
    g_se[pos] = s;
    g_ce[pos] = g_dinv[s] * g_dinv[d];
}

// ---------------- GEMM1: bf16x3 mma + ldmatrix, reg-capped for 2 CTA/SM ----------------
// smem rows pack [hi(32) | lo(32)] bf16, stride 72 elems (144B -> conflict-free ldmatrix)
#define ASTR2 72
__global__ void __launch_bounds__(256, 2) k_gemm1(const float* __restrict__ A, int M) {
    __shared__ __nv_bfloat16 Asm[128 * ASTR2];
    __shared__ __nv_bfloat16 Bsm[128 * ASTR2];
    int tid = threadIdx.x, lane = tid & 31, wid = tid >> 5;
    int bm = blockIdx.y * 128, bn = blockIdx.x * 128;
    int m0 = (wid & 1) * 64, n0 = (wid >> 1) * 32;

    // ldmatrix lane->address bases (bytes)
    uint32_t aBase0 = (uint32_t)__cvta_generic_to_shared(Asm) +
                      (uint32_t)(((m0 + (lane & 15)) * ASTR2 + (lane >> 4) * 8) * 2);
    uint32_t bBase0 = (uint32_t)__cvta_generic_to_shared(Bsm) +
                      (uint32_t)(((n0 + (lane & 7)) * ASTR2 +
                                  ((lane >> 3) & 1) * 8 + (lane >> 4) * 32) * 2);

    float c[4][4][4];
#pragma unroll
    for (int i = 0; i < 4; i++)
#pragma unroll
        for (int j = 0; j < 4; j++)
#pragma unroll
            for (int r = 0; r < 4; r++) c[i][j][r] = 0.0f;

    for (int s = 0; s < F_IN / 32; s++) {
        int k0 = s * 32;
        // A loader: 128 rows x 32 k fp32 -> bf16 hi/lo packed per row (1024 chunks)
#pragma unroll
        for (int i = 0; i < 4; i++) {
            int ch = tid + i * 256;          // 0..1023
            int m = ch >> 3, k4 = ch & 7;
            float4 a = make_float4(0.f, 0.f, 0.f, 0.f);
            if (bm + m < M)
                a = *(const float4*)(A + (size_t)(bm + m) * F_IN + k0 + k4 * 4);
            __nv_bfloat16 hx = __float2bfloat16_rn(a.x), hy = __float2bfloat16_rn(a.y);
            __nv_bfloat16 hz = __float2bfloat16_rn(a.z), hw = __float2bfloat16_rn(a.w);
            __nv_bfloat16 lx = __float2bfloat16_rn(a.x - __bfloat162float(hx));
            __nv_bfloat16 ly = __float2bfloat16_rn(a.y - __bfloat162float(hy));
            __nv_bfloat16 lz = __float2bfloat16_rn(a.z - __bfloat162float(hz));
            __nv_bfloat16 lw = __float2bfloat16_rn(a.w - __bfloat162float(hw));
            *(uint2*)&Asm[m * ASTR2 + k4 * 4]      = make_uint2(pack2(hx, hy), pack2(hz, hw));
            *(uint2*)&Asm[m * ASTR2 + 32 + k4 * 4] = make_uint2(pack2(lx, ly), pack2(lz, lw));
        }
        // B loader: 128 rows x (32 hi + 32 lo) = 8 uint4 chunks/row = 1024 chunks
#pragma unroll
        for (int i = 0; i < 4; i++) {
            int ch = tid + i * 256;          // 0..1023
            int n = ch >> 3, q = ch & 7;
            if (q < 4)
                *(uint4*)&Bsm[n * ASTR2 + q * 8] =
                    *(const uint4*)(g_w1hi + (size_t)(bn + n) * F_IN + k0 + q * 8);
            else
                *(uint4*)&Bsm[n * ASTR2 + 32 + (q - 4) * 8] =
                    *(const uint4*)(g_w1lo + (size_t)(bn + n) * F_IN + k0 + (q - 4) * 8);
        }
        __syncthreads();

#pragma unroll
        for (int kk = 0; kk < 32; kk += 16) {
            uint32_t ah[4][4], al[4][4], bh[4][2], bl[4][2];
#pragma unroll
            for (int tm = 0; tm < 4; tm++) {
                uint32_t aa = aBase0 + (uint32_t)(tm * 16 * ASTR2 * 2 + kk * 2);
                LDSM4(ah[tm][0], ah[tm][1], ah[tm][2], ah[tm][3], aa);
                LDSM4(al[tm][0], al[tm][1], al[tm][2], al[tm][3], aa + 64);
            }
#pragma unroll
            for (int tn = 0; tn < 4; tn++) {
                uint32_t bb = bBase0 + (uint32_t)(tn * 8 * ASTR2 * 2 + kk * 2);
                LDSM4(bh[tn][0], bh[tn][1], bl[tn][0], bl[tn][1], bb);
            }
#pragma unroll
            for (int tm = 0; tm < 4; tm++)
#pragma unroll
                for (int tn = 0; tn < 4; tn++) {
                    MMA_BF16(c[tm][tn], ah[tm], bh[tn]);
                    MMA_BF16(c[tm][tn], ah[tm], bl[tn]);
                    MMA_BF16(c[tm][tn], al[tm], bh[tn]);
                }
        }
        __syncthreads();
    }

#pragma unroll
    for (int tm = 0; tm < 4; tm++) {
        int row0 = bm + m0 + tm * 16 + (lane >> 2);
#pragma unroll
        for (int h = 0; h < 2; h++) {
            int row = row0 + h * 8;
            if (row >= M) continue;
#pragma unroll
            for (int tn = 0; tn < 4; tn++) {
                int col = bn + n0 + tn * 8 + (lane & 3) * 2;
                *(float2*)(g_h1 + (size_t)row * HID + col) =
                    make_float2(c[tm][tn][h * 2 + 0], c[tm][tn][h * 2 + 1]);
            }
        }
    }
}

// ---------------- agg layer 1: block per dst node, unroll 4, no atomics ----------------
__global__ void __launch_bounds__(256) k_agg1(int M) {
    int n = blockIdx.x;
    int tid = threadIdx.x;
    int st = g_rowstart[n], en = g_rowstart[n + 1];
    float dv = g_dinv[n];
    float acc = g_h1[(size_t)n * HID + tid] * (dv * dv);
    int e = st;
    for (; e + 3 < en; e += 4) {
        int s0 = g_se[e], s1 = g_se[e + 1], s2 = g_se[e + 2], s3 = g_se[e + 3];
        float c0 = g_ce[e], c1 = g_ce[e + 1], c2 = g_ce[e + 2], c3 = g_ce[e + 3];
        float v0 = __ldg(g_h1 + (size_t)s0 * HID + tid);
        float v1 = __ldg(g_h1 + (size_t)s1 * HID + tid);
        float v2 = __ldg(g_h1 + (size_t)s2 * HID + tid);
        float v3 = __ldg(g_h1 + (size_t)s3 * HID + tid);
        acc += v0 * c0 + v1 * c1 + v2 * c2 + v3 * c3;
    }
    for (; e < en; e++)
        acc += __ldg(g_h1 + (size_t)g_se[e] * HID + tid) * g_ce[e];
    g_agg1[(size_t)n * HID + tid] = acc;
}

// ---------------- GEMM2 (bias+relu fused A-loader) ----------------
__global__ void __launch_bounds__(256) k_gemm2(const float* __restrict__ W2,
                                               const float* __restrict__ b1, int M) {
    __shared__ float As[32][128];
    __shared__ float Ws[32][NCLS];
    int tid = threadIdx.x;
    int tx = tid & 7, ty = tid >> 3;
    int bm = blockIdx.x * 128;

    float acc[4][5];
#pragma unroll
    for (int i = 0; i < 4; i++)
#pragma unroll
        for (int j = 0; j < 5; j++) acc[i][j] = 0.0f;

    for (int k0 = 0; k0 < HID; k0 += 32) {
#pragma unroll
        for (int i = 0; i < 4; i++) {
            int lin = tid + i * 256;
            int r = lin >> 3, c4 = lin & 7;
            int row = bm + r;
            float4 a4 = make_float4(0.f, 0.f, 0.f, 0.f);
            if (row < M) {
                a4 = *(const float4*)(g_agg1 + (size_t)row * HID + k0 + c4 * 4);
                float4 bb = *(const float4*)(b1 + k0 + c4 * 4);
                a4.x = fmaxf(a4.x + bb.x, 0.0f);
                a4.y = fmaxf(a4.y + bb.y, 0.0f);
                a4.z = fmaxf(a4.z + bb.z, 0.0f);
                a4.w = fmaxf(a4.w + bb.w, 0.0f);
            }
            As[c4 * 4 + 0][r] = a4.x;
            As[c4 * 4 + 1][r] = a4.y;
            As[c4 * 4 + 2][r] = a4.z;
            As[c4 * 4 + 3][r] = a4.w;
        }
#pragma unroll
        for (int i = 0; i < 5; i++) {
            int lin = tid + i * 256;
            int r = lin / NCLS, c = lin % NCLS;
            Ws[r][c] = W2[(size_t)(k0 + r) * NCLS + c];
        }
        __syncthreads();

#pragma unroll
        for (int kk = 0; kk < 32; kk++) {
            float4 a = *(float4*)&As[kk][ty * 4];
            float av[4] = {a.x, a.y, a.z, a.w};
            float w[5];
#pragma unroll
            for (int j = 0; j < 5; j++) w[j] = Ws[kk][tx * 5 + j];
#pragma unroll
            for (int i = 0; i < 4; i++)
#pragma unroll
                for (int j = 0; j < 5; j++)
                    acc[i][j] = fmaf(av[i], w[j], acc[i][j]);
        }
        __syncthreads();
    }

#pragma unroll
    for (int i = 0; i < 4; i++) {
        int row = bm + ty * 4 + i;
        if (row >= M) continue;
#pragma unroll
        for (int j = 0; j < 5; j++)
            g_h2[(size_t)row * NCLS + tx * 5 + j] = acc[i][j];
    }
}

// ---------------- fused agg layer 2 + bias + log_softmax/softmax ----------------
__global__ void __launch_bounds__(256) k_agg2soft(const float* __restrict__ b2,
                                                  float* __restrict__ out,
                                                  int M, int write_soft) {
    int warp = threadIdx.x >> 5, lane = threadIdx.x & 31;
    int n = blockIdx.x * 8 + warp;
    if (n >= M) return;
    int st = g_rowstart[n], en = g_rowstart[n + 1];
    float dv = g_dinv[n];
    float d2 = dv * dv;
    bool has1 = lane < (NCLS - 32);
    const float* hn = g_h2 + (size_t)n * NCLS;
    float a0 = hn[lane] * d2;
    float a1 = has1 ? hn[32 + lane] * d2 : 0.0f;
    for (int e = st; e < en; e++) {
        int s = g_se[e];
        float cc = g_ce[e];
        const float* hs = g_h2 + (size_t)s * NCLS;
        a0 += hs[lane] * cc;
        if (has1) a1 += hs[32 + lane] * cc;
    }
    float v0 = a0 + b2[lane];
    float v1 = has1 ? (a1 + b2[32 + lane]) : -INFINITY;
    float m = fmaxf(v0, v1);
#pragma unroll
    for (int o = 16; o; o >>= 1) m = fmaxf(m, __shfl_xor_sync(0xffffffffu, m, o));
    float s = expf(v0 - m) + (has1 ? expf(v1 - m) : 0.0f);
#pragma unroll
    for (int o = 16; o; o >>= 1) s += __shfl_xor_sync(0xffffffffu, s, o);
    float lse = m + logf(s);
    float l0 = v0 - lse;
    out[(size_t)n * NCLS + lane] = l0;
    if (write_soft) out[(size_t)M * NCLS + (size_t)n * NCLS + lane] = expf(l0);
    if (has1) {
        float l1 = v1 - lse;
        out[(size_t)n * NCLS + lane + 32] = l1;
        if (write_soft) out[(size_t)M * NCLS + (size_t)n * NCLS + lane + 32] = expf(l1);
    }
}

extern "C" void kernel_launch(void* const* d_in, const int* in_sizes, int n_in,
                              void* d_out, int out_size) {
    const float* features = (const float*)d_in[0];
    const float* W1       = (const float*)d_in[1];
    const float* b1       = (const float*)d_in[2];
    const float* W2       = (const float*)d_in[3];
    const float* b2       = (const float*)d_in[4];
    const int*   ei       = (const int*)d_in[5];

    int M = in_sizes[0] / F_IN;
    int E = in_sizes[5] / 2;
    float* out = (float*)d_out;
    int write_soft = (out_size >= 2 * M * NCLS) ? 1 : 0;
    int nb = (M + 1023) / 1024;

    // one-time stream/event setup (first call = uncaptured correctness run)
    static cudaStream_t s2 = 0;
    static cudaEvent_t evFork = 0, evJoin = 0;
    if (!s2) {
        cudaStreamCreateWithFlags(&s2, cudaStreamNonBlocking);
        cudaEventCreateWithFlags(&evFork, cudaEventDisableTiming);
        cudaEventCreateWithFlags(&evJoin, cudaEventDisableTiming);
    }

    // main stream: split W1 (needed by both branches: g_cnt zero + W1 hi/lo)
    k_split_zero<<<(F_IN * HID + 255) / 256, 256>>>(W1);       // launch 1

    // fork: prep chain on s2, GEMM1 on main stream
    cudaEventRecord(evFork, 0);
    cudaStreamWaitEvent(s2, evFork, 0);

    k_count<<<(E + 255) / 256, 256, 0, s2>>>(ei, E);           // launch 2 (s2)
    k_scan1<<<nb, 1024, 0, s2>>>(M);                           // launch 3 (s2)

    dim3 g1(HID / 128, (M + 127) / 128);
    k_gemm1<<<g1, 256>>>(features, M);                         // launch 4 (main) <- profiled

    k_scan2<<<1, 128, 0, s2>>>(nb);                            // launch 5 (s2)
    k_scan3<<<(M + 255) / 256, 256, 0, s2>>>(M, E);            // launch 6 (s2)
    k_bucket<<<(E + 255) / 256, 256, 0, s2>>>(ei, E);          // launch 7 (s2)

    // join: agg1 needs h1 (main) + buckets (s2)
    cudaEventRecord(evJoin, s2);
    cudaStreamWaitEvent(0, evJoin, 0);

    k_agg1<<<M, 256>>>(M);                                     // launch 8
    k_gemm2<<<(M + 127) / 128, 256>>>(W2, b1, M);              // launch 9
    k_agg2soft<<<(M + 7) / 8, 256>>>(b2, out, M, write_soft);  // launch 10
}